// round 4
// baseline (speedup 1.0000x reference)
#include <cuda_runtime.h>
#include <math.h>

#define N_NODES 50000
#define N_EDGES 800000
#define TE 128
#define LDF 36    // feat tile stride (≡4 mod 32 -> conflict-free frag loads)
#define LDV 68    // v / W1 tile stride (≡4 mod 32)
#define LDW 132   // Wkv' tile stride (≡4 mod 32)
#define LDH 68    // node h tile stride (k_node SIMT)

// -------- scratch (static device globals; no allocation) --------
__device__ float g_diff[(size_t)N_EDGES * 12];
__device__ float g_radial[(size_t)N_EDGES * 16];
__device__ float g_qn[(size_t)N_NODES * 64];
__device__ float g_hkv[(size_t)N_NODES * 128];
__device__ float g_hnum[(size_t)N_NODES * 64];
__device__ float g_cnum[(size_t)N_NODES * 12];
__device__ float g_sumsq[16];
__device__ float g_inv[16];
__device__ float g_segsum[N_NODES];

__device__ __forceinline__ void red_add_v4(float* p, float a, float b, float c, float d)
{
    asm volatile("red.global.add.v4.f32 [%0], {%1, %2, %3, %4};"
                 :: "l"(p), "f"(a), "f"(b), "f"(c), "f"(d) : "memory");
}

__device__ __forceinline__ void tf32_split(float x, unsigned& hi, unsigned& lo)
{
    asm("cvt.rna.tf32.f32 %0, %1;" : "=r"(hi) : "f"(x));
    float l = x - __uint_as_float(hi);
    asm("cvt.rna.tf32.f32 %0, %1;" : "=r"(lo) : "f"(l));
}

__device__ __forceinline__ void mma_tf32(float* c, const unsigned* a, unsigned b0, unsigned b1)
{
    asm volatile("mma.sync.aligned.m16n8k8.row.col.f32.tf32.tf32.f32 "
                 "{%0,%1,%2,%3}, {%4,%5,%6,%7}, {%8,%9}, {%0,%1,%2,%3};"
                 : "+f"(c[0]), "+f"(c[1]), "+f"(c[2]), "+f"(c[3])
                 : "r"(a[0]), "r"(a[1]), "r"(a[2]), "r"(a[3]), "r"(b0), "r"(b1));
}

// -------- K0: zero accumulators --------
__global__ void k_init()
{
    int i = blockIdx.x * 256 + threadIdx.x;
    if (i < 3200000) g_hnum[i] = 0.f;
    else if (i < 3800000) g_cnum[i - 3200000] = 0.f;
    else if (i < 3850000) g_segsum[i - 3800000] = 0.f;
    else if (i < 3850016) g_sumsq[i - 3850000] = 0.f;
}

// -------- K1: coord_diff, raw radial, global sum of squares --------
__global__ __launch_bounds__(256) void k_radial(const float* __restrict__ coord,
                                                const int* __restrict__ row,
                                                const int* __restrict__ col)
{
    int e = blockIdx.x * 256 + threadIdx.x;
    float rad[16];
#pragma unroll
    for (int k = 0; k < 16; k++) rad[k] = 0.f;

    if (e < N_EDGES) {
        int r = row[e], c = col[e];
        const float4* pr = (const float4*)(coord + (size_t)r * 12);
        const float4* pc = (const float4*)(coord + (size_t)c * 12);
        float d[12];
#pragma unroll
        for (int q = 0; q < 3; q++) {
            float4 a = pr[q], b = pc[q];
            d[q*4+0] = a.x - b.x; d[q*4+1] = a.y - b.y;
            d[q*4+2] = a.z - b.z; d[q*4+3] = a.w - b.w;
        }
        float4* pd = (float4*)(g_diff + (size_t)e * 12);
        pd[0] = make_float4(d[0], d[1], d[2], d[3]);
        pd[1] = make_float4(d[4], d[5], d[6], d[7]);
        pd[2] = make_float4(d[8], d[9], d[10], d[11]);
#pragma unroll
        for (int ci = 0; ci < 4; ci++)
#pragma unroll
            for (int fi = 0; fi < 4; fi++)
                rad[ci*4+fi] = d[ci*3]*d[fi*3] + d[ci*3+1]*d[fi*3+1] + d[ci*3+2]*d[fi*3+2];
        float4* prad = (float4*)(g_radial + (size_t)e * 16);
        prad[0] = make_float4(rad[0],  rad[1],  rad[2],  rad[3]);
        prad[1] = make_float4(rad[4],  rad[5],  rad[6],  rad[7]);
        prad[2] = make_float4(rad[8],  rad[9],  rad[10], rad[11]);
        prad[3] = make_float4(rad[12], rad[13], rad[14], rad[15]);
    }

    float sq[16];
#pragma unroll
    for (int k = 0; k < 16; k++) sq[k] = rad[k] * rad[k];
#pragma unroll
    for (int off = 16; off > 0; off >>= 1)
#pragma unroll
        for (int k = 0; k < 16; k++)
            sq[k] += __shfl_down_sync(0xffffffffu, sq[k], off);

    __shared__ float red[16];
    if (threadIdx.x < 16) red[threadIdx.x] = 0.f;
    __syncthreads();
    if ((threadIdx.x & 31) == 0) {
#pragma unroll
        for (int k = 0; k < 16; k++) atomicAdd(&red[k], sq[k]);
    }
    __syncthreads();
    if (threadIdx.x < 16) atomicAdd(&g_sumsq[threadIdx.x], red[threadIdx.x]);
}

// -------- K2: inverse norm (16 values) --------
__global__ void k_norm()
{
    int t = threadIdx.x;
    if (t < 16) g_inv[t] = 1.f / fmaxf(sqrtf(g_sumsq[t]), 1e-12f);
}

// -------- K_node: per-node precompute qn = h@Wq + bq, hkv = h@Wkv[16:80] --------
__global__ __launch_bounds__(256, 2) void k_node(
    const float* __restrict__ h,
    const float* __restrict__ Wq, const float* __restrict__ bq,
    const float* __restrict__ Wkv)
{
    extern __shared__ float smn[];
    float* sW = smn;            // 12288: Wq (4096) | Wkv_mid (8192)
    float* sH = smn + 12288;    // 128*LDH = 8704

    const int tid = threadIdx.x;
    const int n0 = blockIdx.x * 128;

    for (int i = tid; i < 1024; i += 256)
        ((float4*)sW)[i] = ((const float4*)Wq)[i];
    for (int i = tid; i < 2048; i += 256)
        ((float4*)(sW + 4096))[i] = ((const float4*)(Wkv + 16 * 128))[i];
    for (int idx = tid; idx < 128 * 16; idx += 256) {
        int n = idx >> 4, c4 = idx & 15;
        float4 v = make_float4(0.f, 0.f, 0.f, 0.f);
        if (n0 + n < N_NODES)
            v = *(const float4*)(h + (size_t)(n0 + n) * 64 + c4 * 4);
        *(float4*)(sH + n * LDH + c4 * 4) = v;
    }
    __syncthreads();

    const int ng = tid >> 4, og = tid & 15;
    const float* hBase = sH + ng * 8 * LDH;

    float accq[8][4];
    {
        float4 b = *(const float4*)(bq + og * 4);
#pragma unroll
        for (int i = 0; i < 8; i++) { accq[i][0]=b.x; accq[i][1]=b.y; accq[i][2]=b.z; accq[i][3]=b.w; }
    }
#pragma unroll 2
    for (int k4 = 0; k4 < 16; k4++) {
        float4 a4[8];
#pragma unroll
        for (int i = 0; i < 8; i++)
            a4[i] = *(const float4*)(hBase + i * LDH + k4 * 4);
#pragma unroll
        for (int kk = 0; kk < 4; kk++) {
            float4 w = *(const float4*)(sW + (k4 * 4 + kk) * 64 + og * 4);
#pragma unroll
            for (int i = 0; i < 8; i++) {
                float a = ((const float*)&a4[i])[kk];
                accq[i][0] += a * w.x; accq[i][1] += a * w.y;
                accq[i][2] += a * w.z; accq[i][3] += a * w.w;
            }
        }
    }
#pragma unroll
    for (int i = 0; i < 8; i++) {
        int n = n0 + ng * 8 + i;
        if (n < N_NODES)
            *(float4*)(g_qn + (size_t)n * 64 + og * 4) =
                make_float4(accq[i][0], accq[i][1], accq[i][2], accq[i][3]);
    }

    float acc[8][8];
#pragma unroll
    for (int i = 0; i < 8; i++)
#pragma unroll
        for (int c = 0; c < 8; c++) acc[i][c] = 0.f;
#pragma unroll 2
    for (int k4 = 0; k4 < 16; k4++) {
#pragma unroll
        for (int half = 0; half < 2; half++) {
            float4 a4[4];
#pragma unroll
            for (int i = 0; i < 4; i++)
                a4[i] = *(const float4*)(hBase + (half * 4 + i) * LDH + k4 * 4);
#pragma unroll
            for (int kk = 0; kk < 4; kk++) {
                const float* wp = sW + 4096 + (k4 * 4 + kk) * 128 + og * 8;
                float4 w0 = *(const float4*)wp;
                float4 w1 = *(const float4*)(wp + 4);
#pragma unroll
                for (int i = 0; i < 4; i++) {
                    float a = ((const float*)&a4[i])[kk];
                    int ii = half * 4 + i;
                    acc[ii][0] += a * w0.x; acc[ii][1] += a * w0.y;
                    acc[ii][2] += a * w0.z; acc[ii][3] += a * w0.w;
                    acc[ii][4] += a * w1.x; acc[ii][5] += a * w1.y;
                    acc[ii][6] += a * w1.z; acc[ii][7] += a * w1.w;
                }
            }
        }
    }
#pragma unroll
    for (int i = 0; i < 8; i++) {
        int n = n0 + ng * 8 + i;
        if (n < N_NODES) {
            float* dst = g_hkv + (size_t)n * 128 + og * 8;
            *(float4*)dst = make_float4(acc[i][0], acc[i][1], acc[i][2], acc[i][3]);
            *(float4*)(dst + 4) = make_float4(acc[i][4], acc[i][5], acc[i][6], acc[i][7]);
        }
    }
}

// -------- K3: fused edge kernel, tensor-core (3xTF32) version --------
// smem float layout:
//   [0)      sWHi (4352 cap: Wkv' 32xLDW=4224, later W1 64xLDV=4352)
//   [4352)   sWLo (4352)
//   [8704)   sA   (8704: feat 128xLDF=4608, later v 128xLDV=8704)
//   [17408)  sEx  (128)
//   [17536)  sU   (512)
//   [18048)  sBKV (128)
//   [18176)  sB1  (64)
//   [18240)  sW2  (256)
//   [18496)  sRow/sCol (256 ints)
// total 18752 floats = 75008 B
__global__ __launch_bounds__(256, 2) void k_fused(
    const float* __restrict__ edge_attr,
    const int* __restrict__ row, const int* __restrict__ col,
    const float* __restrict__ Wkv, const float* __restrict__ bkv,
    const float* __restrict__ W1, const float* __restrict__ b1,
    const float* __restrict__ W2,
    float* __restrict__ ex_out)
{
    extern __shared__ float sm[];
    float* sWHi = sm;
    float* sWLo = sm + 4352;
    float* sA   = sm + 8704;
    float* sEx  = sm + 17408;
    float* sU   = sm + 17536;
    float* sBKV = sm + 18048;
    float* sB1  = sm + 18176;
    float* sW2  = sm + 18240;
    int* sRowS  = (int*)(sm + 18496);
    int* sColS  = sRowS + TE;

    const int tid = threadIdx.x;
    const int e0 = blockIdx.x * TE;

    if (tid < TE) sRowS[tid] = row[e0 + tid];
    else sColS[tid - TE] = col[e0 + tid - TE];

    // stage split Wkv' (rows 0..15 and 80..95 of Wkv), stride LDW
    for (int i = tid; i < 4096; i += 256) {
        int k = i >> 7, n = i & 127;
        int srcr = (k < 16) ? k : (k + 64);
        float w = Wkv[srcr * 128 + n];
        unsigned hi, lo;
        tf32_split(w, hi, lo);
        sWHi[k * LDW + n] = __uint_as_float(hi);
        sWLo[k * LDW + n] = __uint_as_float(lo);
    }
    // stage feat = [radial*inv (16) | edge_attr (16)], fp32, stride LDF
    for (int idx = tid; idx < TE * 8; idx += 256) {
        int e = idx >> 3, c4 = idx & 7;
        float4 v;
        if (c4 < 4) {
            v = *(const float4*)(g_radial + (size_t)(e0 + e) * 16 + c4 * 4);
            float4 inv = *(const float4*)(g_inv + c4 * 4);
            v.x *= inv.x; v.y *= inv.y; v.z *= inv.z; v.w *= inv.w;
        } else {
            v = *(const float4*)(edge_attr + (size_t)(e0 + e) * 16 + (c4 - 4) * 4);
        }
        *(float4*)(sA + e * LDF + c4 * 4) = v;
    }
    // stage bkv / b1 / W2
    if (tid < 32) ((float4*)sBKV)[tid] = ((const float4*)bkv)[tid];
    else if (tid < 48) ((float4*)sB1)[tid - 32] = ((const float4*)b1)[tid - 32];
    else if (tid < 112) ((float4*)sW2)[tid - 48] = ((const float4*)W2)[tid - 48];
    __syncthreads();

    const int wid = tid >> 5, lane = tid & 31;
    const int r = lane >> 2, q = lane & 3;
    const int el0 = wid * 16 + r, el1 = el0 + 8;
    const int nrow0 = sRowS[el0], nrow1 = sRowS[el1];
    const int ncol0 = sColS[el0], ncol1 = sColS[el1];

    // ---- GEMM1: kv = feat @ Wkv' + (bkv + hkv[col]) ----
    float c[16][4];
#pragma unroll
    for (int nt = 0; nt < 16; nt++) {
        int cb = nt * 8 + q * 2;
        float2 bk = *(const float2*)(sBKV + cb);
        float2 h0 = *(const float2*)(g_hkv + (size_t)ncol0 * 128 + cb);
        float2 h1 = *(const float2*)(g_hkv + (size_t)ncol1 * 128 + cb);
        c[nt][0] = bk.x + h0.x; c[nt][1] = bk.y + h0.y;
        c[nt][2] = bk.x + h1.x; c[nt][3] = bk.y + h1.y;
    }
    {
        const float* f0 = sA + el0 * LDF;
        const float* f1 = sA + el1 * LDF;
#pragma unroll
        for (int ks = 0; ks < 4; ks++) {
            int kb = ks * 8;
            unsigned aH[4], aL[4];
            tf32_split(f0[kb + q],     aH[0], aL[0]);
            tf32_split(f1[kb + q],     aH[1], aL[1]);
            tf32_split(f0[kb + 4 + q], aH[2], aL[2]);
            tf32_split(f1[kb + 4 + q], aH[3], aL[3]);
            const float* wh0 = sWHi + (kb + q) * LDW;
            const float* wh1 = sWHi + (kb + 4 + q) * LDW;
            const float* wl0 = sWLo + (kb + q) * LDW;
            const float* wl1 = sWLo + (kb + 4 + q) * LDW;
#pragma unroll
            for (int nt = 0; nt < 16; nt++) {
                int n = nt * 8 + r;
                unsigned bH0 = __float_as_uint(wh0[n]);
                unsigned bH1 = __float_as_uint(wh1[n]);
                unsigned bL0 = __float_as_uint(wl0[n]);
                unsigned bL1 = __float_as_uint(wl1[n]);
                mma_tf32(c[nt], aH, bH0, bH1);
                mma_tf32(c[nt], aL, bH0, bH1);
                mma_tf32(c[nt], aH, bL0, bL1);
            }
        }
    }

    // ---- alpha = qn[row] . k (even cols = c[nt][0]/c[nt][2]) ----
    float pa0 = 0.f, pa1 = 0.f;
#pragma unroll
    for (int nt = 0; nt < 16; nt++) {
        float q0 = __ldg(g_qn + (size_t)nrow0 * 64 + nt * 4 + q);
        float q1 = __ldg(g_qn + (size_t)nrow1 * 64 + nt * 4 + q);
        pa0 += q0 * c[nt][0];
        pa1 += q1 * c[nt][2];
    }
    pa0 += __shfl_xor_sync(0xffffffffu, pa0, 1);
    pa0 += __shfl_xor_sync(0xffffffffu, pa0, 2);
    pa1 += __shfl_xor_sync(0xffffffffu, pa1, 1);
    pa1 += __shfl_xor_sync(0xffffffffu, pa1, 2);
    if (q == 0) {
        float ex0 = __expf(pa0), ex1 = __expf(pa1);   // softmax shift-invariant
        sEx[el0] = ex0; sEx[el1] = ex1;
        ex_out[e0 + el0] = ex0; ex_out[e0 + el1] = ex1;
        atomicAdd(&g_segsum[nrow0], ex0);
        atomicAdd(&g_segsum[nrow1], ex1);
    }
    __syncthreads();   // everyone done reading feat (sA) + Wkv' (sW)

    // ---- v (odd cols) into sA as 128 x LDV; stage split W1 ----
#pragma unroll
    for (int nt = 0; nt < 16; nt++) {
        sA[el0 * LDV + nt * 4 + q] = c[nt][1];
        sA[el1 * LDV + nt * 4 + q] = c[nt][3];
    }
    for (int i = tid; i < 4096; i += 256) {
        int k = i >> 6, n = i & 63;
        float w = W1[i];
        unsigned hi, lo;
        tf32_split(w, hi, lo);
        sWHi[k * LDV + n] = __uint_as_float(hi);
        sWLo[k * LDV + n] = __uint_as_float(lo);
    }
    __syncthreads();

    // ---- MLP1: t = silu(v @ W1 + b1) ----
    float cc[8][4];
#pragma unroll
    for (int nt = 0; nt < 8; nt++) {
        int cb = nt * 8 + q * 2;
        float2 b = *(const float2*)(sB1 + cb);
        cc[nt][0] = b.x; cc[nt][1] = b.y;
        cc[nt][2] = b.x; cc[nt][3] = b.y;
    }
    {
        const float* v0 = sA + el0 * LDV;
        const float* v1 = sA + el1 * LDV;
#pragma unroll
        for (int ks = 0; ks < 8; ks++) {
            int kb = ks * 8;
            unsigned aH[4], aL[4];
            tf32_split(v0[kb + q],     aH[0], aL[0]);
            tf32_split(v1[kb + q],     aH[1], aL[1]);
            tf32_split(v0[kb + 4 + q], aH[2], aL[2]);
            tf32_split(v1[kb + 4 + q], aH[3], aL[3]);
            const float* wh0 = sWHi + (kb + q) * LDV;
            const float* wh1 = sWHi + (kb + 4 + q) * LDV;
            const float* wl0 = sWLo + (kb + q) * LDV;
            const float* wl1 = sWLo + (kb + 4 + q) * LDV;
#pragma unroll
            for (int nt = 0; nt < 8; nt++) {
                int n = nt * 8 + r;
                unsigned bH0 = __float_as_uint(wh0[n]);
                unsigned bH1 = __float_as_uint(wh1[n]);
                unsigned bL0 = __float_as_uint(wl0[n]);
                unsigned bL1 = __float_as_uint(wl1[n]);
                mma_tf32(cc[nt], aH, bH0, bH1);
                mma_tf32(cc[nt], aL, bH0, bH1);
                mma_tf32(cc[nt], aH, bL0, bL1);
            }
        }
    }
#pragma unroll
    for (int nt = 0; nt < 8; nt++)
#pragma unroll
        for (int j = 0; j < 4; j++) {
            float x = cc[nt][j];
            cc[nt][j] = x / (1.f + __expf(-x));
        }

    // ---- MLP2 from fragments: u = t @ W2, quad reduce ----
    float pu0[4] = {0.f, 0.f, 0.f, 0.f};
    float pu1[4] = {0.f, 0.f, 0.f, 0.f};
#pragma unroll
    for (int nt = 0; nt < 8; nt++) {
        int ca = nt * 8 + q * 2;
        float4 wa = *(const float4*)(sW2 + ca * 4);
        float4 wb = *(const float4*)(sW2 + (ca + 1) * 4);
        pu0[0] += cc[nt][0] * wa.x + cc[nt][1] * wb.x;
        pu0[1] += cc[nt][0] * wa.y + cc[nt][1] * wb.y;
        pu0[2] += cc[nt][0] * wa.z + cc[nt][1] * wb.z;
        pu0[3] += cc[nt][0] * wa.w + cc[nt][1] * wb.w;
        pu1[0] += cc[nt][2] * wa.x + cc[nt][3] * wb.x;
        pu1[1] += cc[nt][2] * wa.y + cc[nt][3] * wb.y;
        pu1[2] += cc[nt][2] * wa.z + cc[nt][3] * wb.z;
        pu1[3] += cc[nt][2] * wa.w + cc[nt][3] * wb.w;
    }
#pragma unroll
    for (int off = 1; off <= 2; off <<= 1)
#pragma unroll
        for (int j = 0; j < 4; j++) {
            pu0[j] += __shfl_xor_sync(0xffffffffu, pu0[j], off);
            pu1[j] += __shfl_xor_sync(0xffffffffu, pu1[j], off);
        }
    if (q == 0) {
        *(float4*)(sU + el0 * 4) = make_float4(pu0[0], pu0[1], pu0[2], pu0[3]);
        *(float4*)(sU + el1 * 4) = make_float4(pu1[0], pu1[1], pu1[2], pu1[3]);
    }
    __syncthreads();

    // ---- scatter unnormalized numerators (16B vector atomics) ----
    for (int idx = tid; idx < TE * 16; idx += 256) {
        int e = idx >> 4, c4 = idx & 15;
        float ex = sEx[e];
        float4 v4 = *(const float4*)(sA + e * LDV + c4 * 4);
        red_add_v4(g_hnum + (size_t)sRowS[e] * 64 + c4 * 4,
                   ex * v4.x, ex * v4.y, ex * v4.z, ex * v4.w);
    }
    for (int idx = tid; idx < TE * 3; idx += 256) {
        int e = idx / 3, pp = idx % 3;
        float ex = sEx[e];
        const float* dp = g_diff + (size_t)(e0 + e) * 12 + pp * 4;
        float vals[4];
#pragma unroll
        for (int j = 0; j < 4; j++) {
            int jj = pp * 4 + j;
            int ch = jj / 3;
            vals[j] = dp[j] * (ex * sU[e * 4 + ch]);
        }
        red_add_v4(g_cnum + (size_t)sRowS[e] * 12 + pp * 4,
                   vals[0], vals[1], vals[2], vals[3]);
    }
}

// -------- K4: normalize everything into out --------
__global__ void k_final(const float* __restrict__ h, const float* __restrict__ coord,
                        const int* __restrict__ row, float* __restrict__ out)
{
    int i = blockIdx.x * 256 + threadIdx.x;
    if (i < 3200000) {
        out[i] = h[i] + g_hnum[i] / g_segsum[i >> 6];
    } else if (i < 3800000) {
        int j = i - 3200000;
        out[i] = coord[j] + g_cnum[j] / g_segsum[j / 12];
    } else if (i < 4600000) {
        int e = i - 3800000;
        out[i] = out[i] / g_segsum[row[e]];
    }
}

// -------- launch --------
extern "C" void kernel_launch(void* const* d_in, const int* in_sizes, int n_in,
                              void* d_out, int out_size)
{
    const float *h=0, *coord=0, *edge_attr=0, *Wq=0, *bq=0, *Wkv=0, *bkv=0, *W1=0, *b1=0, *W2=0;
    const int *row=0, *col=0;
    for (int i = 0; i < n_in; i++) {
        int s = in_sizes[i]; const void* p = d_in[i];
        switch (s) {
            case 3200000:  h = (const float*)p; break;
            case 600000:   coord = (const float*)p; break;
            case 800000:   if (!row) row = (const int*)p; else col = (const int*)p; break;
            case 12800000: edge_attr = (const float*)p; break;
            case 4096:     if (!Wq) Wq = (const float*)p; else W1 = (const float*)p; break;
            case 64:       if (!bq) bq = (const float*)p; else b1 = (const float*)p; break;
            case 12288:    Wkv = (const float*)p; break;
            case 128:      bkv = (const float*)p; break;
            case 256:      W2 = (const float*)p; break;
            default: break;
        }
    }
    float* out = (float*)d_out;
    float* att = out + 3800000;

    cudaFuncSetAttribute(k_node,  cudaFuncAttributeMaxDynamicSharedMemorySize, 84992);
    cudaFuncSetAttribute(k_fused, cudaFuncAttributeMaxDynamicSharedMemorySize, 75008);

    k_init<<<(3850016 + 255) / 256, 256>>>();
    k_radial<<<N_EDGES / 256, 256>>>(coord, row, col);
    k_norm<<<1, 16>>>();
    k_node<<<(N_NODES + 127) / 128, 256, 84992>>>(h, Wq, bq, Wkv);
    k_fused<<<N_EDGES / TE, 256, 75008>>>(edge_attr, row, col,
                                          Wkv, bkv, W1, b1, W2, att);
    k_final<<<(4600000 + 255) / 256, 256>>>(h, coord, row, out);
}

// round 5
// speedup vs baseline: 1.1693x; 1.1693x over previous
#include <cuda_runtime.h>
#include <math.h>

#define N_NODES 50000
#define N_EDGES 800000
#define TE 128
#define LDF 36    // feat tile stride (≡4 mod 32 -> conflict-free frag loads)
#define LDV 68    // v / W tile stride (≡4 mod 32)
#define LDH 68    // node h tile stride

// -------- scratch (static device globals; no allocation) --------
__device__ float g_diff[(size_t)N_EDGES * 12];
__device__ float g_qn[(size_t)N_NODES * 64];
__device__ float g_hk[(size_t)N_NODES * 64];   // even kv cols of h@Wkv_mid + bkv_even
__device__ float g_hv[(size_t)N_NODES * 64];   // odd  kv cols of h@Wkv_mid + bkv_odd
__device__ float g_zn[(size_t)N_NODES * 32];   // Wkv_even' @ qn
__device__ float g_hnum[(size_t)N_NODES * 64];
__device__ float g_cnum[(size_t)N_NODES * 12];
__device__ float g_sumsq[16];
__device__ float g_inv[16];
__device__ float g_segsum[N_NODES];

__device__ __forceinline__ void red_add_v4(float* p, float a, float b, float c, float d)
{
    asm volatile("red.global.add.v4.f32 [%0], {%1, %2, %3, %4};"
                 :: "l"(p), "f"(a), "f"(b), "f"(c), "f"(d) : "memory");
}

__device__ __forceinline__ void tf32_split(float x, unsigned& hi, unsigned& lo)
{
    asm("cvt.rna.tf32.f32 %0, %1;" : "=r"(hi) : "f"(x));
    float l = x - __uint_as_float(hi);
    asm("cvt.rna.tf32.f32 %0, %1;" : "=r"(lo) : "f"(l));
}

__device__ __forceinline__ unsigned tf32_hi(float x)
{
    unsigned h;
    asm("cvt.rna.tf32.f32 %0, %1;" : "=r"(h) : "f"(x));
    return h;
}

__device__ __forceinline__ void mma_tf32(float* c, const unsigned* a, unsigned b0, unsigned b1)
{
    asm volatile("mma.sync.aligned.m16n8k8.row.col.f32.tf32.tf32.f32 "
                 "{%0,%1,%2,%3}, {%4,%5,%6,%7}, {%8,%9}, {%0,%1,%2,%3};"
                 : "+f"(c[0]), "+f"(c[1]), "+f"(c[2]), "+f"(c[3])
                 : "r"(a[0]), "r"(a[1]), "r"(a[2]), "r"(a[3]), "r"(b0), "r"(b1));
}

// -------- K0: zero accumulators --------
__global__ void k_init()
{
    int i = blockIdx.x * 256 + threadIdx.x;
    if (i < 3200000) g_hnum[i] = 0.f;
    else if (i < 3800000) g_cnum[i - 3200000] = 0.f;
    else if (i < 3850000) g_segsum[i - 3800000] = 0.f;
    else if (i < 3850016) g_sumsq[i - 3850000] = 0.f;
}

// -------- K1: coord_diff + global sum of squares of radial --------
__global__ __launch_bounds__(256) void k_radial(const float* __restrict__ coord,
                                                const int* __restrict__ row,
                                                const int* __restrict__ col)
{
    int e = blockIdx.x * 256 + threadIdx.x;
    float rad[16];
#pragma unroll
    for (int k = 0; k < 16; k++) rad[k] = 0.f;

    if (e < N_EDGES) {
        int r = row[e], c = col[e];
        const float4* pr = (const float4*)(coord + (size_t)r * 12);
        const float4* pc = (const float4*)(coord + (size_t)c * 12);
        float d[12];
#pragma unroll
        for (int q = 0; q < 3; q++) {
            float4 a = pr[q], b = pc[q];
            d[q*4+0] = a.x - b.x; d[q*4+1] = a.y - b.y;
            d[q*4+2] = a.z - b.z; d[q*4+3] = a.w - b.w;
        }
        float4* pd = (float4*)(g_diff + (size_t)e * 12);
        pd[0] = make_float4(d[0], d[1], d[2], d[3]);
        pd[1] = make_float4(d[4], d[5], d[6], d[7]);
        pd[2] = make_float4(d[8], d[9], d[10], d[11]);
#pragma unroll
        for (int ci = 0; ci < 4; ci++)
#pragma unroll
            for (int fi = 0; fi < 4; fi++)
                rad[ci*4+fi] = d[ci*3]*d[fi*3] + d[ci*3+1]*d[fi*3+1] + d[ci*3+2]*d[fi*3+2];
    }

    float sq[16];
#pragma unroll
    for (int k = 0; k < 16; k++) sq[k] = rad[k] * rad[k];
#pragma unroll
    for (int off = 16; off > 0; off >>= 1)
#pragma unroll
        for (int k = 0; k < 16; k++)
            sq[k] += __shfl_down_sync(0xffffffffu, sq[k], off);

    __shared__ float red[16];
    if (threadIdx.x < 16) red[threadIdx.x] = 0.f;
    __syncthreads();
    if ((threadIdx.x & 31) == 0) {
#pragma unroll
        for (int k = 0; k < 16; k++) atomicAdd(&red[k], sq[k]);
    }
    __syncthreads();
    if (threadIdx.x < 16) atomicAdd(&g_sumsq[threadIdx.x], red[threadIdx.x]);
}

// -------- K2: inverse norm --------
__global__ void k_norm()
{
    int t = threadIdx.x;
    if (t < 16) g_inv[t] = 1.f / fmaxf(sqrtf(g_sumsq[t]), 1e-12f);
}

// -------- K_node: qn, hk/hv (bkv folded), zn = Wkv_even' @ qn --------
__global__ __launch_bounds__(256, 2) void k_node(
    const float* __restrict__ h,
    const float* __restrict__ Wq, const float* __restrict__ bq,
    const float* __restrict__ Wkv, const float* __restrict__ bkv)
{
    extern __shared__ float smn[];
    float* sW = smn;            // 12288: Wq (4096) | Wkv_mid (8192)
    float* sH = smn + 12288;    // 128*LDH = 8704
    float* sWe = smn;           // pass2: Wkv_even' 32x64 = 2048
    float* sQ  = smn + 2048;    // pass2: qn tile 128x68 = 8704

    const int tid = threadIdx.x;
    const int n0 = blockIdx.x * 128;

    for (int i = tid; i < 1024; i += 256)
        ((float4*)sW)[i] = ((const float4*)Wq)[i];
    for (int i = tid; i < 2048; i += 256)
        ((float4*)(sW + 4096))[i] = ((const float4*)(Wkv + 16 * 128))[i];
    for (int idx = tid; idx < 128 * 16; idx += 256) {
        int n = idx >> 4, c4 = idx & 15;
        float4 v = make_float4(0.f, 0.f, 0.f, 0.f);
        if (n0 + n < N_NODES)
            v = *(const float4*)(h + (size_t)(n0 + n) * 64 + c4 * 4);
        *(float4*)(sH + n * LDH + c4 * 4) = v;
    }
    __syncthreads();

    const int ng = tid >> 4, og = tid & 15;
    const float* hBase = sH + ng * 8 * LDH;

    // ---- qn = h@Wq + bq ----
    float accq[8][4];
    {
        float4 b = *(const float4*)(bq + og * 4);
#pragma unroll
        for (int i = 0; i < 8; i++) { accq[i][0]=b.x; accq[i][1]=b.y; accq[i][2]=b.z; accq[i][3]=b.w; }
    }
#pragma unroll 2
    for (int k4 = 0; k4 < 16; k4++) {
        float4 a4[8];
#pragma unroll
        for (int i = 0; i < 8; i++)
            a4[i] = *(const float4*)(hBase + i * LDH + k4 * 4);
#pragma unroll
        for (int kk = 0; kk < 4; kk++) {
            float4 w = *(const float4*)(sW + (k4 * 4 + kk) * 64 + og * 4);
#pragma unroll
            for (int i = 0; i < 8; i++) {
                float a = ((const float*)&a4[i])[kk];
                accq[i][0] += a * w.x; accq[i][1] += a * w.y;
                accq[i][2] += a * w.z; accq[i][3] += a * w.w;
            }
        }
    }
#pragma unroll
    for (int i = 0; i < 8; i++) {
        int n = n0 + ng * 8 + i;
        if (n < N_NODES)
            *(float4*)(g_qn + (size_t)n * 64 + og * 4) =
                make_float4(accq[i][0], accq[i][1], accq[i][2], accq[i][3]);
    }

    // ---- hkv = h@Wkv_mid (+ bkv), split even/odd ----
    float acc[8][8];
#pragma unroll
    for (int i = 0; i < 8; i++)
#pragma unroll
        for (int c = 0; c < 8; c++) acc[i][c] = 0.f;
#pragma unroll 2
    for (int k4 = 0; k4 < 16; k4++) {
#pragma unroll
        for (int half = 0; half < 2; half++) {
            float4 a4[4];
#pragma unroll
            for (int i = 0; i < 4; i++)
                a4[i] = *(const float4*)(hBase + (half * 4 + i) * LDH + k4 * 4);
#pragma unroll
            for (int kk = 0; kk < 4; kk++) {
                const float* wp = sW + 4096 + (k4 * 4 + kk) * 128 + og * 8;
                float4 w0 = *(const float4*)wp;
                float4 w1 = *(const float4*)(wp + 4);
#pragma unroll
                for (int i = 0; i < 4; i++) {
                    float a = ((const float*)&a4[i])[kk];
                    int ii = half * 4 + i;
                    acc[ii][0] += a * w0.x; acc[ii][1] += a * w0.y;
                    acc[ii][2] += a * w0.z; acc[ii][3] += a * w0.w;
                    acc[ii][4] += a * w1.x; acc[ii][5] += a * w1.y;
                    acc[ii][6] += a * w1.z; acc[ii][7] += a * w1.w;
                }
            }
        }
    }
    {
        float bk[8];
#pragma unroll
        for (int c = 0; c < 8; c++) bk[c] = __ldg(bkv + og * 8 + c);
#pragma unroll
        for (int i = 0; i < 8; i++) {
            int n = n0 + ng * 8 + i;
            if (n < N_NODES) {
                *(float4*)(g_hk + (size_t)n * 64 + og * 4) =
                    make_float4(acc[i][0]+bk[0], acc[i][2]+bk[2], acc[i][4]+bk[4], acc[i][6]+bk[6]);
                *(float4*)(g_hv + (size_t)n * 64 + og * 4) =
                    make_float4(acc[i][1]+bk[1], acc[i][3]+bk[3], acc[i][5]+bk[5], acc[i][7]+bk[7]);
            }
        }
    }
    __syncthreads();

    // ---- pass2: zn = Wkv_even' @ qn ----
    for (int i = tid; i < 2048; i += 256) {
        int k = i >> 6, j = i & 63;
        int srcr = (k < 16) ? k : (k + 64);
        sWe[k * 64 + j] = Wkv[srcr * 128 + 2 * j];
    }
#pragma unroll
    for (int i = 0; i < 8; i++)
        *(float4*)(sQ + (ng * 8 + i) * 68 + og * 4) =
            make_float4(accq[i][0], accq[i][1], accq[i][2], accq[i][3]);
    __syncthreads();

    {
        int n = tid >> 1, kh = (tid & 1) * 16;
        if (n0 + n < N_NODES) {
            const float* qrow = sQ + n * 68;
            float zres[16];
#pragma unroll
            for (int k = 0; k < 16; k++) {
                const float* we = sWe + (kh + k) * 64;
                float s = 0.f;
#pragma unroll
                for (int j4 = 0; j4 < 16; j4++) {
                    float4 w = *(const float4*)(we + j4 * 4);
                    float4 qv = *(const float4*)(qrow + j4 * 4);
                    s += w.x*qv.x + w.y*qv.y + w.z*qv.z + w.w*qv.w;
                }
                zres[k] = s;
            }
            float4* zp = (float4*)(g_zn + (size_t)(n0 + n) * 32 + kh);
#pragma unroll
            for (int k4 = 0; k4 < 4; k4++)
                zp[k4] = make_float4(zres[k4*4], zres[k4*4+1], zres[k4*4+2], zres[k4*4+3]);
        }
    }
}

// -------- K3: fused edge kernel --------
// alpha in exact fp32 via zn trick; v GEMM 3xTF32; MLP1 1xTF32; scatter numerators.
// smem floats: sWHi 4352 | sWLo 2176 | sA 8704 | sP 256 | sEx 128 | sU 512
//              | sB1 64 | sW2 256 | sRow/sCol 256 ints  -> 16704 floats = 66816 B
__global__ __launch_bounds__(256, 2) void k_fused(
    const float* __restrict__ edge_attr,
    const int* __restrict__ row, const int* __restrict__ col,
    const float* __restrict__ Wkv,
    const float* __restrict__ W1, const float* __restrict__ b1,
    const float* __restrict__ W2,
    float* __restrict__ ex_out)
{
    extern __shared__ float sm[];
    float* sWHi = sm;
    float* sWLo = sm + 4352;
    float* sA   = sm + 6528;
    float* sP   = sm + 15232;
    float* sEx  = sm + 15488;
    float* sU   = sm + 15616;
    float* sB1  = sm + 16128;
    float* sW2  = sm + 16192;
    int* sRowS  = (int*)(sm + 16448);
    int* sColS  = sRowS + TE;

    const int tid = threadIdx.x;
    const int e0 = blockIdx.x * TE;

    if (tid < TE) sRowS[tid] = row[e0 + tid];
    else sColS[tid - TE] = col[e0 + tid - TE];

    // stage Wkv_odd' split (32 x 64)
    for (int i = tid; i < 2048; i += 256) {
        int k = i >> 6, n = i & 63;
        int srcr = (k < 16) ? k : (k + 64);
        unsigned hi, lo;
        tf32_split(Wkv[srcr * 128 + 2 * n + 1], hi, lo);
        sWHi[k * LDV + n] = __uint_as_float(hi);
        sWLo[k * LDV + n] = __uint_as_float(lo);
    }
    // stage feat = [radial*inv (16, recomputed from diff) | edge_attr (16)]
    for (int idx = tid; idx < TE * 8; idx += 256) {
        int e = idx >> 3, c4 = idx & 7;
        float4 v;
        if (c4 < 4) {
            const float4* pd = (const float4*)(g_diff + (size_t)(e0 + e) * 12);
            float4 d0 = pd[0], d1 = pd[1], d2 = pd[2];
            float d[12] = {d0.x,d0.y,d0.z,d0.w, d1.x,d1.y,d1.z,d1.w, d2.x,d2.y,d2.z,d2.w};
            float4 inv = *(const float4*)(g_inv + c4 * 4);
            const float* dc = d + c4 * 3;
            v.x = (dc[0]*d[0] + dc[1]*d[1]  + dc[2]*d[2])  * inv.x;
            v.y = (dc[0]*d[3] + dc[1]*d[4]  + dc[2]*d[5])  * inv.y;
            v.z = (dc[0]*d[6] + dc[1]*d[7]  + dc[2]*d[8])  * inv.z;
            v.w = (dc[0]*d[9] + dc[1]*d[10] + dc[2]*d[11]) * inv.w;
        } else {
            v = *(const float4*)(edge_attr + (size_t)(e0 + e) * 16 + (c4 - 4) * 4);
        }
        *(float4*)(sA + e * LDF + c4 * 4) = v;
    }
    if (tid < 16) ((float4*)sB1)[tid] = ((const float4*)b1)[tid];
    else if (tid < 80) ((float4*)sW2)[tid - 16] = ((const float4*)W2)[tid - 16];
    __syncthreads();

    // ---- alpha partials (exact fp32): 2 threads per edge ----
    {
        int e = tid >> 1, hf = tid & 1;
        int nr = sRowS[e], nc = sColS[e];
        const float4* qp = (const float4*)(g_qn + (size_t)nr * 64 + hf * 32);
        const float4* kp = (const float4*)(g_hk + (size_t)nc * 64 + hf * 32);
        const float4* zp = (const float4*)(g_zn + (size_t)nr * 32 + hf * 16);
        const float* fp = sA + e * LDF + hf * 16;
        float p = 0.f;
#pragma unroll
        for (int j = 0; j < 8; j++) {
            float4 a = qp[j], b = kp[j];
            p += a.x*b.x + a.y*b.y + a.z*b.z + a.w*b.w;
        }
#pragma unroll
        for (int j = 0; j < 4; j++) {
            float4 z = zp[j];
            float4 f = *(const float4*)(fp + j * 4);
            p += z.x*f.x + z.y*f.y + z.z*f.z + z.w*f.w;
        }
        sP[tid] = p;
    }

    const int wid = tid >> 5, lane = tid & 31;
    const int r = lane >> 2, q = lane & 3;
    const int el0 = wid * 16 + r, el1 = el0 + 8;
    const int ncol0 = sColS[el0], ncol1 = sColS[el1];

    // ---- v = hv[col] + feat @ Wkv_odd' (3xTF32) ----
    float c[8][4];
#pragma unroll
    for (int nt = 0; nt < 8; nt++) {
        int cb = nt * 8 + q * 2;
        float2 h0 = *(const float2*)(g_hv + (size_t)ncol0 * 64 + cb);
        float2 h1 = *(const float2*)(g_hv + (size_t)ncol1 * 64 + cb);
        c[nt][0] = h0.x; c[nt][1] = h0.y; c[nt][2] = h1.x; c[nt][3] = h1.y;
    }
    {
        const float* f0 = sA + el0 * LDF;
        const float* f1 = sA + el1 * LDF;
#pragma unroll
        for (int ks = 0; ks < 4; ks++) {
            int kb = ks * 8;
            unsigned aH[4], aL[4];
            tf32_split(f0[kb + q],     aH[0], aL[0]);
            tf32_split(f1[kb + q],     aH[1], aL[1]);
            tf32_split(f0[kb + 4 + q], aH[2], aL[2]);
            tf32_split(f1[kb + 4 + q], aH[3], aL[3]);
            const float* wh0 = sWHi + (kb + q) * LDV;
            const float* wh1 = sWHi + (kb + 4 + q) * LDV;
            const float* wl0 = sWLo + (kb + q) * LDV;
            const float* wl1 = sWLo + (kb + 4 + q) * LDV;
#pragma unroll
            for (int nt = 0; nt < 8; nt++) {
                int n = nt * 8 + r;
                unsigned bH0 = __float_as_uint(wh0[n]);
                unsigned bH1 = __float_as_uint(wh1[n]);
                mma_tf32(c[nt], aH, bH0, bH1);
                mma_tf32(c[nt], aL, bH0, bH1);
                mma_tf32(c[nt], aH, __float_as_uint(wl0[n]), __float_as_uint(wl1[n]));
            }
        }
    }
    __syncthreads();   // all feat/W reads + sP writes complete

    // ---- v tile into sA (stride LDV); stage W1 (hi only); exp + segsum ----
#pragma unroll
    for (int nt = 0; nt < 8; nt++) {
        int cb = nt * 8 + q * 2;
        *(float2*)(sA + el0 * LDV + cb) = make_float2(c[nt][0], c[nt][1]);
        *(float2*)(sA + el1 * LDV + cb) = make_float2(c[nt][2], c[nt][3]);
    }
    for (int i = tid; i < 4096; i += 256) {
        int k = i >> 6, n = i & 63;
        sWHi[k * LDV + n] = __uint_as_float(tf32_hi(W1[i]));
    }
    if (tid < TE) {
        float al = sP[2 * tid] + sP[2 * tid + 1];
        float ex = __expf(al);          // softmax shift-invariant; |alpha| bounded
        sEx[tid] = ex;
        ex_out[e0 + tid] = ex;          // normalized in k_final
        atomicAdd(&g_segsum[sRowS[tid]], ex);
    }
    __syncthreads();

    // ---- MLP1: t = silu(v @ W1 + b1), single-pass TF32 (feeds coord only) ----
    float cc[8][4];
#pragma unroll
    for (int nt = 0; nt < 8; nt++) {
        int cb = nt * 8 + q * 2;
        float2 b = *(const float2*)(sB1 + cb);
        cc[nt][0] = b.x; cc[nt][1] = b.y; cc[nt][2] = b.x; cc[nt][3] = b.y;
    }
    {
        const float* v0 = sA + el0 * LDV;
        const float* v1 = sA + el1 * LDV;
#pragma unroll
        for (int ks = 0; ks < 8; ks++) {
            int kb = ks * 8;
            unsigned aH[4];
            aH[0] = tf32_hi(v0[kb + q]);
            aH[1] = tf32_hi(v1[kb + q]);
            aH[2] = tf32_hi(v0[kb + 4 + q]);
            aH[3] = tf32_hi(v1[kb + 4 + q]);
            const float* wh0 = sWHi + (kb + q) * LDV;
            const float* wh1 = sWHi + (kb + 4 + q) * LDV;
#pragma unroll
            for (int nt = 0; nt < 8; nt++) {
                int n = nt * 8 + r;
                mma_tf32(cc[nt], aH, __float_as_uint(wh0[n]), __float_as_uint(wh1[n]));
            }
        }
    }
#pragma unroll
    for (int nt = 0; nt < 8; nt++)
#pragma unroll
        for (int j = 0; j < 4; j++) {
            float x = cc[nt][j];
            cc[nt][j] = x / (1.f + __expf(-x));
        }

    // ---- MLP2: u = t @ W2, quad reduce ----
    float pu0[4] = {0.f, 0.f, 0.f, 0.f};
    float pu1[4] = {0.f, 0.f, 0.f, 0.f};
#pragma unroll
    for (int nt = 0; nt < 8; nt++) {
        int ca = nt * 8 + q * 2;
        float4 wa = *(const float4*)(sW2 + ca * 4);
        float4 wb = *(const float4*)(sW2 + (ca + 1) * 4);
        pu0[0] += cc[nt][0]*wa.x + cc[nt][1]*wb.x;
        pu0[1] += cc[nt][0]*wa.y + cc[nt][1]*wb.y;
        pu0[2] += cc[nt][0]*wa.z + cc[nt][1]*wb.z;
        pu0[3] += cc[nt][0]*wa.w + cc[nt][1]*wb.w;
        pu1[0] += cc[nt][2]*wa.x + cc[nt][3]*wb.x;
        pu1[1] += cc[nt][2]*wa.y + cc[nt][3]*wb.y;
        pu1[2] += cc[nt][2]*wa.z + cc[nt][3]*wb.z;
        pu1[3] += cc[nt][2]*wa.w + cc[nt][3]*wb.w;
    }
#pragma unroll
    for (int off = 1; off <= 2; off <<= 1)
#pragma unroll
        for (int j = 0; j < 4; j++) {
            pu0[j] += __shfl_xor_sync(0xffffffffu, pu0[j], off);
            pu1[j] += __shfl_xor_sync(0xffffffffu, pu1[j], off);
        }
    if (q == 0) {
        *(float4*)(sU + el0 * 4) = make_float4(pu0[0], pu0[1], pu0[2], pu0[3]);
        *(float4*)(sU + el1 * 4) = make_float4(pu1[0], pu1[1], pu1[2], pu1[3]);
    }
    __syncthreads();

    // ---- scatter unnormalized numerators (16B vector atomics) ----
    for (int idx = tid; idx < TE * 16; idx += 256) {
        int e = idx >> 4, c4 = idx & 15;
        float ex = sEx[e];
        float4 v4 = *(const float4*)(sA + e * LDV + c4 * 4);
        red_add_v4(g_hnum + (size_t)sRowS[e] * 64 + c4 * 4,
                   ex * v4.x, ex * v4.y, ex * v4.z, ex * v4.w);
    }
    for (int idx = tid; idx < TE * 3; idx += 256) {
        int e = idx / 3, pp = idx % 3;
        float ex = sEx[e];
        const float* dp = g_diff + (size_t)(e0 + e) * 12 + pp * 4;
        float vals[4];
#pragma unroll
        for (int j = 0; j < 4; j++) {
            int jj = pp * 4 + j;
            int ch = jj / 3;
            vals[j] = dp[j] * (ex * sU[e * 4 + ch]);
        }
        red_add_v4(g_cnum + (size_t)sRowS[e] * 12 + pp * 4,
                   vals[0], vals[1], vals[2], vals[3]);
    }
}

// -------- K4: normalize everything into out --------
__global__ void k_final(const float* __restrict__ h, const float* __restrict__ coord,
                        const int* __restrict__ row, float* __restrict__ out)
{
    int i = blockIdx.x * 256 + threadIdx.x;
    if (i < 3200000) {
        out[i] = h[i] + g_hnum[i] / g_segsum[i >> 6];
    } else if (i < 3800000) {
        int j = i - 3200000;
        out[i] = coord[j] + g_cnum[j] / g_segsum[j / 12];
    } else if (i < 4600000) {
        int e = i - 3800000;
        out[i] = out[i] / g_segsum[row[e]];
    }
}

// -------- launch --------
extern "C" void kernel_launch(void* const* d_in, const int* in_sizes, int n_in,
                              void* d_out, int out_size)
{
    const float *h=0, *coord=0, *edge_attr=0, *Wq=0, *bq=0, *Wkv=0, *bkv=0, *W1=0, *b1=0, *W2=0;
    const int *row=0, *col=0;
    for (int i = 0; i < n_in; i++) {
        int s = in_sizes[i]; const void* p = d_in[i];
        switch (s) {
            case 3200000:  h = (const float*)p; break;
            case 600000:   coord = (const float*)p; break;
            case 800000:   if (!row) row = (const int*)p; else col = (const int*)p; break;
            case 12800000: edge_attr = (const float*)p; break;
            case 4096:     if (!Wq) Wq = (const float*)p; else W1 = (const float*)p; break;
            case 64:       if (!bq) bq = (const float*)p; else b1 = (const float*)p; break;
            case 12288:    Wkv = (const float*)p; break;
            case 128:      bkv = (const float*)p; break;
            case 256:      W2 = (const float*)p; break;
            default: break;
        }
    }
    float* out = (float*)d_out;
    float* att = out + 3800000;

    cudaFuncSetAttribute(k_node,  cudaFuncAttributeMaxDynamicSharedMemorySize, 84992);
    cudaFuncSetAttribute(k_fused, cudaFuncAttributeMaxDynamicSharedMemorySize, 66816);

    k_init<<<(3850016 + 255) / 256, 256>>>();
    k_radial<<<N_EDGES / 256, 256>>>(coord, row, col);
    k_norm<<<1, 16>>>();
    k_node<<<(N_NODES + 127) / 128, 256, 84992>>>(h, Wq, bq, Wkv, bkv);
    k_fused<<<N_EDGES / TE, 256, 66816>>>(edge_attr, row, col,
                                          Wkv, W1, b1, W2, att);
    k_final<<<(4600000 + 255) / 256, 256>>>(h, coord, row, out);
}

// round 6
// speedup vs baseline: 1.2674x; 1.0839x over previous
#include <cuda_runtime.h>
#include <math.h>

#define N_NODES 50000
#define N_EDGES 800000
#define TE 128
#define LDF 36    // feat tile stride (≡4 mod 32)
#define LDV 68    // v / W tile stride (≡4 mod 32)
#define LDH 68    // node h tile stride

// -------- scratch (static device globals; no allocation) --------
__device__ float g_qn[(size_t)N_NODES * 64];
__device__ float g_hk[(size_t)N_NODES * 64];   // even kv cols of h@Wkv_mid + bkv_even
__device__ float g_hv[(size_t)N_NODES * 64];   // odd  kv cols of h@Wkv_mid + bkv_odd
__device__ float g_zn[(size_t)N_NODES * 32];   // Wkv_even' @ qn
__device__ float g_WoHi[32 * 64];              // split Wkv_odd' hi
__device__ float g_WoLo[32 * 64];              // split Wkv_odd' lo
__device__ float g_W1t[64 * 64];               // tf32-rounded W1
__device__ float g_hnum[(size_t)N_NODES * 64];
__device__ float g_cnum[(size_t)N_NODES * 12];
__device__ float g_sumsq[16];
__device__ float g_inv[16];
__device__ float g_segsum[N_NODES];

__device__ __forceinline__ void red_add_v4(float* p, float a, float b, float c, float d)
{
    asm volatile("red.global.add.v4.f32 [%0], {%1, %2, %3, %4};"
                 :: "l"(p), "f"(a), "f"(b), "f"(c), "f"(d) : "memory");
}

__device__ __forceinline__ void tf32_split(float x, unsigned& hi, unsigned& lo)
{
    asm("cvt.rna.tf32.f32 %0, %1;" : "=r"(hi) : "f"(x));
    float l = x - __uint_as_float(hi);
    asm("cvt.rna.tf32.f32 %0, %1;" : "=r"(lo) : "f"(l));
}

__device__ __forceinline__ unsigned tf32_hi(float x)
{
    unsigned h;
    asm("cvt.rna.tf32.f32 %0, %1;" : "=r"(h) : "f"(x));
    return h;
}

__device__ __forceinline__ void mma_tf32(float* c, const unsigned* a, unsigned b0, unsigned b1)
{
    asm volatile("mma.sync.aligned.m16n8k8.row.col.f32.tf32.tf32.f32 "
                 "{%0,%1,%2,%3}, {%4,%5,%6,%7}, {%8,%9}, {%0,%1,%2,%3};"
                 : "+f"(c[0]), "+f"(c[1]), "+f"(c[2]), "+f"(c[3])
                 : "r"(a[0]), "r"(a[1]), "r"(a[2]), "r"(a[3]), "r"(b0), "r"(b1));
}

// -------- K0: zero accumulators + precompute weight transforms --------
__global__ void k_init(const float* __restrict__ Wkv, const float* __restrict__ W1)
{
    int i = blockIdx.x * 256 + threadIdx.x;
    if (i < 3200000) g_hnum[i] = 0.f;
    else if (i < 3800000) g_cnum[i - 3200000] = 0.f;
    else if (i < 3850000) g_segsum[i - 3800000] = 0.f;
    else if (i < 3850016) g_sumsq[i - 3850000] = 0.f;
    else if (i < 3852064) {
        int j = i - 3850016;
        int k = j >> 6, n = j & 63;
        int srcr = (k < 16) ? k : (k + 64);
        unsigned hi, lo;
        tf32_split(Wkv[srcr * 128 + 2 * n + 1], hi, lo);
        g_WoHi[j] = __uint_as_float(hi);
        g_WoLo[j] = __uint_as_float(lo);
    } else if (i < 3856160) {
        int j = i - 3852064;
        g_W1t[j] = __uint_as_float(tf32_hi(W1[j]));
    }
}

// -------- K1: global sum of squares of radial (no diff store) --------
__global__ __launch_bounds__(256) void k_radial(const float* __restrict__ coord,
                                                const int* __restrict__ row,
                                                const int* __restrict__ col)
{
    int e = blockIdx.x * 256 + threadIdx.x;
    float rad[16];
#pragma unroll
    for (int k = 0; k < 16; k++) rad[k] = 0.f;

    if (e < N_EDGES) {
        int r = row[e], c = col[e];
        const float4* pr = (const float4*)(coord + (size_t)r * 12);
        const float4* pc = (const float4*)(coord + (size_t)c * 12);
        float d[12];
#pragma unroll
        for (int q = 0; q < 3; q++) {
            float4 a = pr[q], b = pc[q];
            d[q*4+0] = a.x - b.x; d[q*4+1] = a.y - b.y;
            d[q*4+2] = a.z - b.z; d[q*4+3] = a.w - b.w;
        }
#pragma unroll
        for (int ci = 0; ci < 4; ci++)
#pragma unroll
            for (int fi = 0; fi < 4; fi++)
                rad[ci*4+fi] = d[ci*3]*d[fi*3] + d[ci*3+1]*d[fi*3+1] + d[ci*3+2]*d[fi*3+2];
    }

    float sq[16];
#pragma unroll
    for (int k = 0; k < 16; k++) sq[k] = rad[k] * rad[k];
#pragma unroll
    for (int off = 16; off > 0; off >>= 1)
#pragma unroll
        for (int k = 0; k < 16; k++)
            sq[k] += __shfl_down_sync(0xffffffffu, sq[k], off);

    __shared__ float red[16];
    if (threadIdx.x < 16) red[threadIdx.x] = 0.f;
    __syncthreads();
    if ((threadIdx.x & 31) == 0) {
#pragma unroll
        for (int k = 0; k < 16; k++) atomicAdd(&red[k], sq[k]);
    }
    __syncthreads();
    if (threadIdx.x < 16) atomicAdd(&g_sumsq[threadIdx.x], red[threadIdx.x]);
}

// -------- K2: inverse norm --------
__global__ void k_norm()
{
    int t = threadIdx.x;
    if (t < 16) g_inv[t] = 1.f / fmaxf(sqrtf(g_sumsq[t]), 1e-12f);
}

// -------- K_node: qn, hk/hv (bkv folded), zn = Wkv_even' @ qn --------
__global__ __launch_bounds__(256, 2) void k_node(
    const float* __restrict__ h,
    const float* __restrict__ Wq, const float* __restrict__ bq,
    const float* __restrict__ Wkv, const float* __restrict__ bkv)
{
    extern __shared__ float smn[];
    float* sW = smn;            // 12288: Wq (4096) | Wkv_mid (8192)
    float* sH = smn + 12288;    // 128*LDH = 8704
    float* sWe = smn;           // pass2: Wkv_even' 32x64 = 2048
    float* sQ  = smn + 2048;    // pass2: qn tile 128x68 = 8704

    const int tid = threadIdx.x;
    const int n0 = blockIdx.x * 128;

    for (int i = tid; i < 1024; i += 256)
        ((float4*)sW)[i] = ((const float4*)Wq)[i];
    for (int i = tid; i < 2048; i += 256)
        ((float4*)(sW + 4096))[i] = ((const float4*)(Wkv + 16 * 128))[i];
    for (int idx = tid; idx < 128 * 16; idx += 256) {
        int n = idx >> 4, c4 = idx & 15;
        float4 v = make_float4(0.f, 0.f, 0.f, 0.f);
        if (n0 + n < N_NODES)
            v = *(const float4*)(h + (size_t)(n0 + n) * 64 + c4 * 4);
        *(float4*)(sH + n * LDH + c4 * 4) = v;
    }
    __syncthreads();

    const int ng = tid >> 4, og = tid & 15;
    const float* hBase = sH + ng * 8 * LDH;

    float accq[8][4];
    {
        float4 b = *(const float4*)(bq + og * 4);
#pragma unroll
        for (int i = 0; i < 8; i++) { accq[i][0]=b.x; accq[i][1]=b.y; accq[i][2]=b.z; accq[i][3]=b.w; }
    }
#pragma unroll 2
    for (int k4 = 0; k4 < 16; k4++) {
        float4 a4[8];
#pragma unroll
        for (int i = 0; i < 8; i++)
            a4[i] = *(const float4*)(hBase + i * LDH + k4 * 4);
#pragma unroll
        for (int kk = 0; kk < 4; kk++) {
            float4 w = *(const float4*)(sW + (k4 * 4 + kk) * 64 + og * 4);
#pragma unroll
            for (int i = 0; i < 8; i++) {
                float a = ((const float*)&a4[i])[kk];
                accq[i][0] += a * w.x; accq[i][1] += a * w.y;
                accq[i][2] += a * w.z; accq[i][3] += a * w.w;
            }
        }
    }
#pragma unroll
    for (int i = 0; i < 8; i++) {
        int n = n0 + ng * 8 + i;
        if (n < N_NODES)
            *(float4*)(g_qn + (size_t)n * 64 + og * 4) =
                make_float4(accq[i][0], accq[i][1], accq[i][2], accq[i][3]);
    }

    float acc[8][8];
#pragma unroll
    for (int i = 0; i < 8; i++)
#pragma unroll
        for (int c = 0; c < 8; c++) acc[i][c] = 0.f;
#pragma unroll 2
    for (int k4 = 0; k4 < 16; k4++) {
#pragma unroll
        for (int half = 0; half < 2; half++) {
            float4 a4[4];
#pragma unroll
            for (int i = 0; i < 4; i++)
                a4[i] = *(const float4*)(hBase + (half * 4 + i) * LDH + k4 * 4);
#pragma unroll
            for (int kk = 0; kk < 4; kk++) {
                const float* wp = sW + 4096 + (k4 * 4 + kk) * 128 + og * 8;
                float4 w0 = *(const float4*)wp;
                float4 w1 = *(const float4*)(wp + 4);
#pragma unroll
                for (int i = 0; i < 4; i++) {
                    float a = ((const float*)&a4[i])[kk];
                    int ii = half * 4 + i;
                    acc[ii][0] += a * w0.x; acc[ii][1] += a * w0.y;
                    acc[ii][2] += a * w0.z; acc[ii][3] += a * w0.w;
                    acc[ii][4] += a * w1.x; acc[ii][5] += a * w1.y;
                    acc[ii][6] += a * w1.z; acc[ii][7] += a * w1.w;
                }
            }
        }
    }
    {
        float bk[8];
#pragma unroll
        for (int c = 0; c < 8; c++) bk[c] = __ldg(bkv + og * 8 + c);
#pragma unroll
        for (int i = 0; i < 8; i++) {
            int n = n0 + ng * 8 + i;
            if (n < N_NODES) {
                *(float4*)(g_hk + (size_t)n * 64 + og * 4) =
                    make_float4(acc[i][0]+bk[0], acc[i][2]+bk[2], acc[i][4]+bk[4], acc[i][6]+bk[6]);
                *(float4*)(g_hv + (size_t)n * 64 + og * 4) =
                    make_float4(acc[i][1]+bk[1], acc[i][3]+bk[3], acc[i][5]+bk[5], acc[i][7]+bk[7]);
            }
        }
    }
    __syncthreads();

    // ---- pass2: zn = Wkv_even' @ qn ----
    for (int i = tid; i < 2048; i += 256) {
        int k = i >> 6, j = i & 63;
        int srcr = (k < 16) ? k : (k + 64);
        sWe[k * 64 + j] = Wkv[srcr * 128 + 2 * j];
    }
#pragma unroll
    for (int i = 0; i < 8; i++)
        *(float4*)(sQ + (ng * 8 + i) * 68 + og * 4) =
            make_float4(accq[i][0], accq[i][1], accq[i][2], accq[i][3]);
    __syncthreads();

    {
        int n = tid >> 1, kh = (tid & 1) * 16;
        if (n0 + n < N_NODES) {
            const float* qrow = sQ + n * 68;
            float zres[16];
#pragma unroll
            for (int k = 0; k < 16; k++) {
                const float* we = sWe + (kh + k) * 64;
                float s = 0.f;
#pragma unroll
                for (int j4 = 0; j4 < 16; j4++) {
                    float4 w = *(const float4*)(we + j4 * 4);
                    float4 qv = *(const float4*)(qrow + j4 * 4);
                    s += w.x*qv.x + w.y*qv.y + w.z*qv.z + w.w*qv.w;
                }
                zres[k] = s;
            }
            float4* zp = (float4*)(g_zn + (size_t)(n0 + n) * 32 + kh);
#pragma unroll
            for (int k4 = 0; k4 < 4; k4++)
                zp[k4] = make_float4(zres[k4*4], zres[k4*4+1], zres[k4*4+2], zres[k4*4+3]);
        }
    }
}

// -------- K3: fused edge kernel --------
__global__ __launch_bounds__(256, 2) void k_fused(
    const float* __restrict__ coord, const float* __restrict__ edge_attr,
    const int* __restrict__ row, const int* __restrict__ col,
    const float* __restrict__ b1, const float* __restrict__ W2,
    float* __restrict__ ex_out)
{
    extern __shared__ float sm[];
    float* sWHi = sm;             // 4352 (Wo' hi 32xLDV, later W1t 64xLDV)
    float* sWLo = sm + 4352;      // 2176
    float* sA   = sm + 6528;      // 8704: feat 128xLDF, then v 128xLDV
    float* sP   = sm + 15232;     // 256
    float* sEx  = sm + 15488;     // 128
    float* sU   = sm + 15616;     // 512
    float* sB1  = sm + 16128;     // 64
    float* sW2  = sm + 16192;     // 256
    int* sRowS  = (int*)(sm + 16448);
    int* sColS  = sRowS + TE;

    const int tid = threadIdx.x;
    const int e0 = blockIdx.x * TE;

    if (tid < TE) sRowS[tid] = row[e0 + tid];
    else sColS[tid - TE] = col[e0 + tid - TE];

    // stage precomputed split Wkv_odd' (vectorized)
    for (int i = tid; i < 512; i += 256) {
        int k = i >> 4, n4 = i & 15;
        *(float4*)(sWHi + k * LDV + n4 * 4) = ((const float4*)g_WoHi)[i];
        *(float4*)(sWLo + k * LDV + n4 * 4) = ((const float4*)g_WoLo)[i];
    }
    // radial recompute from coord (1 thread / edge), write feat[0:16]
    if (tid < TE) {
        int e = tid;
        int nr = row[e0 + e], nc = col[e0 + e];
        const float4* pr = (const float4*)(coord + (size_t)nr * 12);
        const float4* pc = (const float4*)(coord + (size_t)nc * 12);
        float d[12];
#pragma unroll
        for (int q2 = 0; q2 < 3; q2++) {
            float4 a = pr[q2], b = pc[q2];
            d[q2*4+0] = a.x - b.x; d[q2*4+1] = a.y - b.y;
            d[q2*4+2] = a.z - b.z; d[q2*4+3] = a.w - b.w;
        }
#pragma unroll
        for (int ci = 0; ci < 4; ci++) {
            float4 v;
            const float* dc = d + ci * 3;
            v.x = dc[0]*d[0] + dc[1]*d[1]  + dc[2]*d[2];
            v.y = dc[0]*d[3] + dc[1]*d[4]  + dc[2]*d[5];
            v.z = dc[0]*d[6] + dc[1]*d[7]  + dc[2]*d[8];
            v.w = dc[0]*d[9] + dc[1]*d[10] + dc[2]*d[11];
            float4 inv = *(const float4*)(g_inv + ci * 4);
            v.x *= inv.x; v.y *= inv.y; v.z *= inv.z; v.w *= inv.w;
            *(float4*)(sA + e * LDF + ci * 4) = v;
        }
    }
    // edge_attr into feat[16:32]
    for (int idx = tid; idx < TE * 4; idx += 256) {
        int e = idx >> 2, c4 = idx & 3;
        *(float4*)(sA + e * LDF + 16 + c4 * 4) =
            *(const float4*)(edge_attr + (size_t)(e0 + e) * 16 + c4 * 4);
    }
    if (tid < 16) ((float4*)sB1)[tid] = ((const float4*)b1)[tid];
    else if (tid < 80) ((float4*)sW2)[tid - 16] = ((const float4*)W2)[tid - 16];
    __syncthreads();

    // ---- alpha partials (exact fp32): 2 threads per edge ----
    {
        int e = tid >> 1, hf = tid & 1;
        int nr = sRowS[e], nc = sColS[e];
        const float4* qp = (const float4*)(g_qn + (size_t)nr * 64 + hf * 32);
        const float4* kp = (const float4*)(g_hk + (size_t)nc * 64 + hf * 32);
        const float4* zp = (const float4*)(g_zn + (size_t)nr * 32 + hf * 16);
        const float* fp = sA + e * LDF + hf * 16;
        float p = 0.f;
#pragma unroll
        for (int j = 0; j < 8; j++) {
            float4 a = qp[j], b = kp[j];
            p += a.x*b.x + a.y*b.y + a.z*b.z + a.w*b.w;
        }
#pragma unroll
        for (int j = 0; j < 4; j++) {
            float4 z = zp[j];
            float4 f = *(const float4*)(fp + j * 4);
            p += z.x*f.x + z.y*f.y + z.z*f.z + z.w*f.w;
        }
        sP[tid] = p;
    }

    const int wid = tid >> 5, lane = tid & 31;
    const int r = lane >> 2, q = lane & 3;
    const int el0 = wid * 16 + r, el1 = el0 + 8;

    // ---- v_gemm = feat @ Wkv_odd' (3xTF32), acc from 0 ----
    float c[8][4];
#pragma unroll
    for (int nt = 0; nt < 8; nt++) { c[nt][0]=0.f; c[nt][1]=0.f; c[nt][2]=0.f; c[nt][3]=0.f; }
    {
        const float* f0 = sA + el0 * LDF;
        const float* f1 = sA + el1 * LDF;
#pragma unroll
        for (int ks = 0; ks < 4; ks++) {
            int kb = ks * 8;
            unsigned aH[4], aL[4];
            tf32_split(f0[kb + q],     aH[0], aL[0]);
            tf32_split(f1[kb + q],     aH[1], aL[1]);
            tf32_split(f0[kb + 4 + q], aH[2], aL[2]);
            tf32_split(f1[kb + 4 + q], aH[3], aL[3]);
            const float* wh0 = sWHi + (kb + q) * LDV;
            const float* wh1 = sWHi + (kb + 4 + q) * LDV;
            const float* wl0 = sWLo + (kb + q) * LDV;
            const float* wl1 = sWLo + (kb + 4 + q) * LDV;
#pragma unroll
            for (int nt = 0; nt < 8; nt++) {
                int n = nt * 8 + r;
                unsigned bH0 = __float_as_uint(wh0[n]);
                unsigned bH1 = __float_as_uint(wh1[n]);
                mma_tf32(c[nt], aH, bH0, bH1);
                mma_tf32(c[nt], aL, bH0, bH1);
                mma_tf32(c[nt], aH, __float_as_uint(wl0[n]), __float_as_uint(wl1[n]));
            }
        }
    }
    __syncthreads();   // feat/W reads + sP writes complete

    // ---- v fragments into sA (stride LDV); exp + segsum ----
#pragma unroll
    for (int nt = 0; nt < 8; nt++) {
        int cb = nt * 8 + q * 2;
        *(float2*)(sA + el0 * LDV + cb) = make_float2(c[nt][0], c[nt][1]);
        *(float2*)(sA + el1 * LDV + cb) = make_float2(c[nt][2], c[nt][3]);
    }
    if (tid < TE) {
        float al = sP[2 * tid] + sP[2 * tid + 1];
        float ex = __expf(al);          // softmax shift-invariant; |alpha| bounded
        sEx[tid] = ex;
        ex_out[e0 + tid] = ex;
        atomicAdd(&g_segsum[sRowS[tid]], ex);
    }
    __syncthreads();

    // ---- add hv[col] (coalesced float4 gathers); stage W1t ----
    for (int idx = tid; idx < TE * 16; idx += 256) {
        int e = idx >> 4, c4 = idx & 15;
        float4 hv4 = *(const float4*)(g_hv + (size_t)sColS[e] * 64 + c4 * 4);
        float* vp = sA + e * LDV + c4 * 4;
        vp[0] += hv4.x; vp[1] += hv4.y; vp[2] += hv4.z; vp[3] += hv4.w;
    }
    for (int i = tid; i < 1024; i += 256) {
        int k = i >> 4, n4 = i & 15;
        *(float4*)(sWHi + k * LDV + n4 * 4) = ((const float4*)g_W1t)[i];
    }
    __syncthreads();

    // ---- MLP1: t = silu(v @ W1 + b1), single-pass TF32 (feeds coord only) ----
    float cc[8][4];
#pragma unroll
    for (int nt = 0; nt < 8; nt++) {
        int cb = nt * 8 + q * 2;
        float2 b = *(const float2*)(sB1 + cb);
        cc[nt][0] = b.x; cc[nt][1] = b.y; cc[nt][2] = b.x; cc[nt][3] = b.y;
    }
    {
        const float* v0 = sA + el0 * LDV;
        const float* v1 = sA + el1 * LDV;
#pragma unroll
        for (int ks = 0; ks < 8; ks++) {
            int kb = ks * 8;
            unsigned aH[4];
            aH[0] = tf32_hi(v0[kb + q]);
            aH[1] = tf32_hi(v1[kb + q]);
            aH[2] = tf32_hi(v0[kb + 4 + q]);
            aH[3] = tf32_hi(v1[kb + 4 + q]);
            const float* wh0 = sWHi + (kb + q) * LDV;
            const float* wh1 = sWHi + (kb + 4 + q) * LDV;
#pragma unroll
            for (int nt = 0; nt < 8; nt++) {
                int n = nt * 8 + r;
                mma_tf32(cc[nt], aH, __float_as_uint(wh0[n]), __float_as_uint(wh1[n]));
            }
        }
    }
#pragma unroll
    for (int nt = 0; nt < 8; nt++)
#pragma unroll
        for (int j = 0; j < 4; j++) {
            float x = cc[nt][j];
            cc[nt][j] = x / (1.f + __expf(-x));
        }

    // ---- MLP2: u = t @ W2, quad reduce ----
    float pu0[4] = {0.f, 0.f, 0.f, 0.f};
    float pu1[4] = {0.f, 0.f, 0.f, 0.f};
#pragma unroll
    for (int nt = 0; nt < 8; nt++) {
        int ca = nt * 8 + q * 2;
        float4 wa = *(const float4*)(sW2 + ca * 4);
        float4 wb = *(const float4*)(sW2 + (ca + 1) * 4);
        pu0[0] += cc[nt][0]*wa.x + cc[nt][1]*wb.x;
        pu0[1] += cc[nt][0]*wa.y + cc[nt][1]*wb.y;
        pu0[2] += cc[nt][0]*wa.z + cc[nt][1]*wb.z;
        pu0[3] += cc[nt][0]*wa.w + cc[nt][1]*wb.w;
        pu1[0] += cc[nt][2]*wa.x + cc[nt][3]*wb.x;
        pu1[1] += cc[nt][2]*wa.y + cc[nt][3]*wb.y;
        pu1[2] += cc[nt][2]*wa.z + cc[nt][3]*wb.z;
        pu1[3] += cc[nt][2]*wa.w + cc[nt][3]*wb.w;
    }
#pragma unroll
    for (int off = 1; off <= 2; off <<= 1)
#pragma unroll
        for (int j = 0; j < 4; j++) {
            pu0[j] += __shfl_xor_sync(0xffffffffu, pu0[j], off);
            pu1[j] += __shfl_xor_sync(0xffffffffu, pu1[j], off);
        }
    if (q == 0) {
        *(float4*)(sU + el0 * 4) = make_float4(pu0[0], pu0[1], pu0[2], pu0[3]);
        *(float4*)(sU + el1 * 4) = make_float4(pu1[0], pu1[1], pu1[2], pu1[3]);
    }
    __syncthreads();

    // ---- scatter unnormalized numerators (16B vector atomics) ----
    for (int idx = tid; idx < TE * 16; idx += 256) {
        int e = idx >> 4, c4 = idx & 15;
        float ex = sEx[e];
        float4 v4 = *(const float4*)(sA + e * LDV + c4 * 4);
        red_add_v4(g_hnum + (size_t)sRowS[e] * 64 + c4 * 4,
                   ex * v4.x, ex * v4.y, ex * v4.z, ex * v4.w);
    }
    for (int idx = tid; idx < TE * 3; idx += 256) {
        int e = idx / 3, pp = idx % 3;
        float ex = sEx[e];
        float4 cr = *(const float4*)(coord + (size_t)sRowS[e] * 12 + pp * 4);
        float4 cl = *(const float4*)(coord + (size_t)sColS[e] * 12 + pp * 4);
        float dp[4] = {cr.x - cl.x, cr.y - cl.y, cr.z - cl.z, cr.w - cl.w};
        float vals[4];
#pragma unroll
        for (int j = 0; j < 4; j++) {
            int jj = pp * 4 + j;
            int ch = jj / 3;
            vals[j] = dp[j] * (ex * sU[e * 4 + ch]);
        }
        red_add_v4(g_cnum + (size_t)sRowS[e] * 12 + pp * 4,
                   vals[0], vals[1], vals[2], vals[3]);
    }
}

// -------- K4: normalize everything into out --------
__global__ void k_final(const float* __restrict__ h, const float* __restrict__ coord,
                        const int* __restrict__ row, float* __restrict__ out)
{
    int i = blockIdx.x * 256 + threadIdx.x;
    if (i < 3200000) {
        out[i] = h[i] + g_hnum[i] / g_segsum[i >> 6];
    } else if (i < 3800000) {
        int j = i - 3200000;
        out[i] = coord[j] + g_cnum[j] / g_segsum[j / 12];
    } else if (i < 4600000) {
        int e = i - 3800000;
        out[i] = out[i] / g_segsum[row[e]];
    }
}

// -------- launch --------
extern "C" void kernel_launch(void* const* d_in, const int* in_sizes, int n_in,
                              void* d_out, int out_size)
{
    const float *h=0, *coord=0, *edge_attr=0, *Wq=0, *bq=0, *Wkv=0, *bkv=0, *W1=0, *b1=0, *W2=0;
    const int *row=0, *col=0;
    for (int i = 0; i < n_in; i++) {
        int s = in_sizes[i]; const void* p = d_in[i];
        switch (s) {
            case 3200000:  h = (const float*)p; break;
            case 600000:   coord = (const float*)p; break;
            case 800000:   if (!row) row = (const int*)p; else col = (const int*)p; break;
            case 12800000: edge_attr = (const float*)p; break;
            case 4096:     if (!Wq) Wq = (const float*)p; else W1 = (const float*)p; break;
            case 64:       if (!bq) bq = (const float*)p; else b1 = (const float*)p; break;
            case 12288:    Wkv = (const float*)p; break;
            case 128:      bkv = (const float*)p; break;
            case 256:      W2 = (const float*)p; break;
            default: break;
        }
    }
    float* out = (float*)d_out;
    float* att = out + 3800000;

    cudaFuncSetAttribute(k_node,  cudaFuncAttributeMaxDynamicSharedMemorySize, 84992);
    cudaFuncSetAttribute(k_fused, cudaFuncAttributeMaxDynamicSharedMemorySize, 66816);

    k_init<<<(3856160 + 255) / 256, 256>>>(Wkv, W1);
    k_radial<<<N_EDGES / 256, 256>>>(coord, row, col);
    k_norm<<<1, 16>>>();
    k_node<<<(N_NODES + 127) / 128, 256, 84992>>>(h, Wq, bq, Wkv, bkv);
    k_fused<<<N_EDGES / TE, 256, 66816>>>(coord, edge_attr, row, col, b1, W2, att);
    k_final<<<(4600000 + 255) / 256, 256>>>(h, coord, row, out);
}